// round 8
// baseline (speedup 1.0000x reference)
#include <cuda_runtime.h>

// Leapfrog (KDK), softened point mass: a = -q / (r*(r+1)^2 + 1e-12).
//
// v8: FFMA-pipe was identified as the binding resource (rt_SMSP=2; measured
// dur == FFMA-count x rt2 at ~1.1GHz with issue% = slots/FFMA-cycles). Halve
// it with fma.rn.f32x2: one thread integrates the (trail,lead) PAIR packed in
// f32x2 lanes. Unlike R2:
//  - the entire step (drift, r2, denominator chain, kick) stays packed; we
//    unpack only at the two rsqrt sites (mov.b64 reg-pair aliasing ~free),
//  - rsqrt-only MUFU path, full unroll of the 63 interior steps, dt = x/64.
// Pipe model per SMSP: FFMA2 ~6.3K cyc, MUFU ~7.2K cyc -> MUFU-limited,
// vs 12.6K FFMA-limited for the scalar v7.
//
// Inputs: d_in[0]=ts f32[N], d_in[1]=w0_lead f32[N,6], d_in[2]=w0_trail f32[N,6],
//         d_in[3]=n_steps i32. Output f32[2N,6]: row 2i=trail_i, 2i+1=lead_i.

typedef unsigned long long u64;

__device__ __forceinline__ u64 pk2(float lo, float hi) {
    u64 r; asm("mov.b64 %0, {%1, %2};" : "=l"(r) : "f"(lo), "f"(hi)); return r;
}
__device__ __forceinline__ void upk2(u64 v, float& lo, float& hi) {
    asm("mov.b64 {%0, %1}, %2;" : "=f"(lo), "=f"(hi) : "l"(v));
}
__device__ __forceinline__ u64 fma2(u64 a, u64 b, u64 c) {
    u64 d; asm("fma.rn.f32x2 %0, %1, %2, %3;" : "=l"(d) : "l"(a), "l"(b), "l"(c)); return d;
}
__device__ __forceinline__ u64 mul2(u64 a, u64 b) {
    u64 d; asm("mul.rn.f32x2 %0, %1, %2;" : "=l"(d) : "l"(a), "l"(b)); return d;
}
__device__ __forceinline__ float rsqrt_ap(float x) {
    float r; asm("rsqrt.approx.f32 %0, %1;" : "=f"(r) : "f"(x)); return r;
}
__device__ __forceinline__ u64 rsqrt2(u64 v) {
    float a, b; upk2(v, a, b);
    return pk2(rsqrt_ap(a), rsqrt_ap(b));
}

struct State { u64 qx, qy, qz, px, py, pz; };

// p += coef * accel(q); ncoef2 = packed(-coef) folds accel's sign.
// 14 FFMA2-class ops + 4 MUFU per call (covers 2 particles).
__device__ __forceinline__ void kick(State& s, u64 ncoef2, u64 two2) {
    u64 r2  = fma2(s.qx, s.qx, fma2(s.qy, s.qy, mul2(s.qz, s.qz)));
    u64 u   = rsqrt2(r2);               // 1/r
    u64 r   = mul2(r2, u);              // r
    u64 t   = fma2(r, r2, r);           // r*r2 + r
    u64 den = fma2(two2, r2, t);        // r(r+1)^2
    u64 inv = rsqrt2(mul2(den, den));   // 1/den (den > 0)
    u64 sc  = mul2(inv, ncoef2);        // -coef/den
    s.px = fma2(sc, s.qx, s.px);
    s.py = fma2(sc, s.qy, s.py);
    s.pz = fma2(sc, s.qz, s.pz);
}

__device__ __forceinline__ void drift(State& s, u64 dt2) {
    s.qx = fma2(dt2, s.px, s.qx);
    s.qy = fma2(dt2, s.py, s.qy);
    s.qz = fma2(dt2, s.pz, s.qz);
}

template <int INTERIOR, bool FULL_UNROLL>
__device__ __forceinline__ void integrate(State& s, float dt, int interior_rt) {
    u64 dt2  = pk2(dt, dt);
    u64 ndt2 = pk2(-dt, -dt);
    u64 nh2  = pk2(-0.5f * dt, -0.5f * dt);
    u64 two2 = pk2(2.0f, 2.0f);

    kick(s, nh2, two2);
    if (FULL_UNROLL) {
        #pragma unroll
        for (int it = 0; it < INTERIOR; ++it) { drift(s, dt2); kick(s, ndt2, two2); }
    } else {
        #pragma unroll 4
        for (int it = 0; it < interior_rt; ++it) { drift(s, dt2); kick(s, ndt2, two2); }
    }
    drift(s, dt2);
    kick(s, nh2, two2);
}

__global__ void __launch_bounds__(64)
leapfrog_v8_kernel(const float* __restrict__ ts,
                   const float* __restrict__ w0_lead,
                   const float* __restrict__ w0_trail,
                   const int*   __restrict__ n_steps_ptr,
                   float* __restrict__ out,
                   int N) {
    int i = blockIdx.x * blockDim.x + threadIdx.x;
    if (i >= N) return;

    int n_steps = *n_steps_ptr;
    float t_f = ts[N - 1] + 0.001f;

    // Load both rows; pack lo=trail, hi=lead.
    const float2* __restrict__ rl = reinterpret_cast<const float2*>(w0_lead  + 6 * i);
    const float2* __restrict__ rt = reinterpret_cast<const float2*>(w0_trail + 6 * i);
    float2 l0 = rl[0], l1 = rl[1], l2 = rl[2];
    float2 t0 = rt[0], t1 = rt[1], t2 = rt[2];

    State s;
    s.qx = pk2(t0.x, l0.x);  s.qy = pk2(t0.y, l0.y);  s.qz = pk2(t1.x, l1.x);
    s.px = pk2(t1.y, l1.y);  s.py = pk2(t2.x, l2.x);  s.pz = pk2(t2.y, l2.y);

    if (n_steps == 64) {
        float dt = (t_f - ts[i]) * 0.015625f;   // exact /64
        integrate<63, true>(s, dt, 63);
    } else {
        float dt = (t_f - ts[i]) / (float)n_steps;
        integrate<0, false>(s, dt, n_steps - 1);
    }

    // Unpack and store rows 2i (trail), 2i+1 (lead): 48 contiguous bytes.
    float qxt, qxl, qyt, qyl, qzt, qzl, pxt, pxl, pyt, pyl, pzt, pzl;
    upk2(s.qx, qxt, qxl); upk2(s.qy, qyt, qyl); upk2(s.qz, qzt, qzl);
    upk2(s.px, pxt, pxl); upk2(s.py, pyt, pyl); upk2(s.pz, pzt, pzl);

    float4* __restrict__ o = reinterpret_cast<float4*>(out + 12 * i);
    o[0] = make_float4(qxt, qyt, qzt, pxt);
    o[1] = make_float4(pyt, pzt, qxl, qyl);
    o[2] = make_float4(qzl, pxl, pyl, pzl);
}

extern "C" void kernel_launch(void* const* d_in, const int* in_sizes, int n_in,
                              void* d_out, int out_size) {
    const float* ts       = (const float*)d_in[0];
    const float* w0_lead  = (const float*)d_in[1];
    const float* w0_trail = (const float*)d_in[2];
    const int*   n_steps  = (const int*)d_in[3];
    float* out = (float*)d_out;

    int N = in_sizes[0];
    int threads = 64;                   // 1024 CTAs -> 6.92/SM, +-7% balance
    int blocks = (N + threads - 1) / threads;
    leapfrog_v8_kernel<<<blocks, threads>>>(ts, w0_lead, w0_trail, n_steps, out, N);
}

// round 9
// speedup vs baseline: 1.1604x; 1.1604x over previous
#include <cuda_runtime.h>

// Leapfrog (KDK), softened point mass: a = -q / (r*(r+1)^2 + 1e-12).
//
// v9 = v7 launch/unroll (scalar, 2N threads, block=64 -> 2048 balanced CTAs,
// 63 interior steps fully unrolled, dt = x * 2^-6) with a 2-FFMA-leaner kick:
//   r   = sqrt.approx(r2)        (MUFU.SQRT, replaces rsqrt+mul)
//   den = fma(r, r2, fma(2, r2, r))   // r + 2 r2 + r*r2 = r(1+r)^2
//   inv = rcp.approx(den)        (MUFU.RCP, replaces mul+rsqrt)
// 12 FFMA-pipe + 2 MUFU per interior step vs v7's 14+2. FFMA is the binding
// pipe (~70% busy; f32x2 proven useless in R8 — pipe-time conserved), so
// -13% FFMA instructions should move duration nearly proportionally.
//
// Inputs: d_in[0]=ts f32[N], d_in[1]=w0_lead f32[N,6], d_in[2]=w0_trail f32[N,6],
//         d_in[3]=n_steps i32. Output f32[2N,6]: row 2i=trail_i, 2i+1=lead_i.

__device__ __forceinline__ float sqrt_ap(float x) {
    float r; asm("sqrt.approx.f32 %0, %1;" : "=f"(r) : "f"(x)); return r;
}
__device__ __forceinline__ float rcp_ap(float x) {
    float r; asm("rcp.approx.f32 %0, %1;" : "=f"(r) : "f"(x)); return r;
}

// p += coef * accel(q); ncoef pre-negated (-coef) folds accel's sign.
// 9 FFMA-pipe + 2 MUFU.
__device__ __forceinline__ void kick(float& qx, float& qy, float& qz,
                                     float& px, float& py, float& pz,
                                     float ncoef) {
    float r2  = fmaf(qx, qx, fmaf(qy, qy, qz * qz));
    float r   = sqrt_ap(r2);                      // MUFU.SQRT
    float den = fmaf(r, r2, fmaf(2.0f, r2, r));   // r(1+r)^2
    float sc  = rcp_ap(den) * ncoef;              // MUFU.RCP; -coef/den
    px = fmaf(sc, qx, px);
    py = fmaf(sc, qy, py);
    pz = fmaf(sc, qz, pz);
}

__device__ __forceinline__ void drift(float& qx, float& qy, float& qz,
                                      float px, float py, float pz, float dt) {
    qx = fmaf(dt, px, qx);
    qy = fmaf(dt, py, qy);
    qz = fmaf(dt, pz, qz);
}

template <int INTERIOR, bool FULL_UNROLL>
__device__ __forceinline__ void integrate(float& qx, float& qy, float& qz,
                                          float& px, float& py, float& pz,
                                          float dt, int interior_rt) {
    float nhdt = -0.5f * dt;
    float ndt  = -dt;

    kick(qx, qy, qz, px, py, pz, nhdt);
    if (FULL_UNROLL) {
        #pragma unroll
        for (int s = 0; s < INTERIOR; ++s) {
            drift(qx, qy, qz, px, py, pz, dt);
            kick(qx, qy, qz, px, py, pz, ndt);
        }
    } else {
        #pragma unroll 4
        for (int s = 0; s < interior_rt; ++s) {
            drift(qx, qy, qz, px, py, pz, dt);
            kick(qx, qy, qz, px, py, pz, ndt);
        }
    }
    drift(qx, qy, qz, px, py, pz, dt);
    kick(qx, qy, qz, px, py, pz, nhdt);
}

__global__ void __launch_bounds__(64)
leapfrog_v9_kernel(const float* __restrict__ ts,
                   const float* __restrict__ w0_lead,
                   const float* __restrict__ w0_trail,
                   const int*   __restrict__ n_steps_ptr,
                   float* __restrict__ out,
                   int N) {
    int tid = blockIdx.x * blockDim.x + threadIdx.x;
    if (tid >= 2 * N) return;

    int b = (tid >= N) ? 1 : 0;        // 0 = trail, 1 = lead
    int i = tid - b * N;

    const float* __restrict__ w0 = b ? w0_lead : w0_trail;

    int n_steps = *n_steps_ptr;
    float t_f = ts[N - 1] + 0.001f;    // broadcast, L2-resident

    const float2* __restrict__ row = reinterpret_cast<const float2*>(w0 + 6 * i);
    float2 v0 = row[0];
    float2 v1 = row[1];
    float2 v2 = row[2];
    float qx = v0.x, qy = v0.y, qz = v1.x;
    float px = v1.y, py = v2.x, pz = v2.y;

    if (n_steps == 64) {
        float dt = (t_f - ts[i]) * 0.015625f;   // exact /64
        integrate<63, true>(qx, qy, qz, px, py, pz, dt, 63);
    } else {
        float dt = (t_f - ts[i]) / (float)n_steps;
        integrate<0, false>(qx, qy, qz, px, py, pz, dt, n_steps - 1);
    }

    int orow = 2 * i + b;
    float2* __restrict__ orow_p = reinterpret_cast<float2*>(out + 6 * orow);
    orow_p[0] = make_float2(qx, qy);
    orow_p[1] = make_float2(qz, px);
    orow_p[2] = make_float2(py, pz);
}

extern "C" void kernel_launch(void* const* d_in, const int* in_sizes, int n_in,
                              void* d_out, int out_size) {
    const float* ts       = (const float*)d_in[0];
    const float* w0_lead  = (const float*)d_in[1];
    const float* w0_trail = (const float*)d_in[2];
    const int*   n_steps  = (const int*)d_in[3];
    float* out = (float*)d_out;

    int N = in_sizes[0];
    int total = 2 * N;
    int threads = 64;                   // 2048 CTAs -> balanced 13-14 per SM
    int blocks = (total + threads - 1) / threads;
    leapfrog_v9_kernel<<<blocks, threads>>>(ts, w0_lead, w0_trail, n_steps, out, N);
}